// round 1
// baseline (speedup 1.0000x reference)
#include <cuda_runtime.h>
#include <cstdint>

// Problem constants (fixed by the reference)
#define B_DIM 1024
#define T_DIM 256
#define D_DIM 1024
#define NUM_LABELS 8
#define NUM_PROTOS 64   // per label; M = 512 total

// Device scratch (no cudaMalloc allowed)
__device__ float g_c[NUM_LABELS * D_DIM];   // c_l[d] = mean_p w[8p+l][d]   (32 KB)
__device__ float g_sqpart[NUM_LABELS * 4];  // partial sums of w^2 per (l, d-chunk)

// ---------------------------------------------------------------------------
// Prep: fold prototype_weight [512, 1024] into c[8][1024] and sqpart[8][4].
// Grid: 32 blocks (l = blk>>2, chunk = blk&3), 256 threads (one d each).
// ---------------------------------------------------------------------------
__global__ void proto_fold_kernel(const float* __restrict__ w) {
    const int l     = blockIdx.x >> 2;
    const int chunk = blockIdx.x & 3;
    const int d     = chunk * 256 + threadIdx.x;

    float sum = 0.0f, sq = 0.0f;
#pragma unroll 8
    for (int p = 0; p < NUM_PROTOS; ++p) {
        float v = w[(size_t)((p << 3) + l) * D_DIM + d];
        sum += v;
        sq  += v * v;
    }
    g_c[l * D_DIM + d] = sum * (1.0f / NUM_PROTOS);

    // block-reduce sq
    __shared__ float red[256];
    red[threadIdx.x] = sq;
    __syncthreads();
    for (int s = 128; s > 0; s >>= 1) {
        if (threadIdx.x < s) red[threadIdx.x] += red[threadIdx.x + s];
        __syncthreads();
    }
    if (threadIdx.x == 0) g_sqpart[blockIdx.x] = red[0];
}

// ---------------------------------------------------------------------------
// Main: one block per batch row b.
//   a[b,:] = (1/T) sum_t h[b,t,:]        (streamed, 256 KB per block)
//   out[b,l] = 2 * a.c_l - ||a||^2 - s_l
// 256 threads; each thread owns 4 consecutive d's (float4).
// ---------------------------------------------------------------------------
__global__ __launch_bounds__(256, 8)
void pool_proto_kernel(const float* __restrict__ h, float* __restrict__ out) {
    const int b   = blockIdx.x;
    const int tid = threadIdx.x;

    // Base: float4 view of h[b, 0, tid*4]
    const float4* hp = reinterpret_cast<const float4*>(h)
                       + (size_t)b * T_DIM * (D_DIM / 4) + tid;

    float4 s0 = {0,0,0,0}, s1 = {0,0,0,0}, s2 = {0,0,0,0}, s3 = {0,0,0,0};

    // Stream T=256 rows, unroll 8 -> MLP=8 per thread, __ldcs (no reuse)
#pragma unroll 4
    for (int t = 0; t < T_DIM; t += 8) {
        float4 v0 = __ldcs(hp + (size_t)(t + 0) * 256);
        float4 v1 = __ldcs(hp + (size_t)(t + 1) * 256);
        float4 v2 = __ldcs(hp + (size_t)(t + 2) * 256);
        float4 v3 = __ldcs(hp + (size_t)(t + 3) * 256);
        float4 v4 = __ldcs(hp + (size_t)(t + 4) * 256);
        float4 v5 = __ldcs(hp + (size_t)(t + 5) * 256);
        float4 v6 = __ldcs(hp + (size_t)(t + 6) * 256);
        float4 v7 = __ldcs(hp + (size_t)(t + 7) * 256);
        s0.x += v0.x; s0.y += v0.y; s0.z += v0.z; s0.w += v0.w;
        s1.x += v1.x; s1.y += v1.y; s1.z += v1.z; s1.w += v1.w;
        s2.x += v2.x; s2.y += v2.y; s2.z += v2.z; s2.w += v2.w;
        s3.x += v3.x; s3.y += v3.y; s3.z += v3.z; s3.w += v3.w;
        s0.x += v4.x; s0.y += v4.y; s0.z += v4.z; s0.w += v4.w;
        s1.x += v5.x; s1.y += v5.y; s1.z += v5.z; s1.w += v5.w;
        s2.x += v6.x; s2.y += v6.y; s2.z += v6.z; s2.w += v6.w;
        s3.x += v7.x; s3.y += v7.y; s3.z += v7.z; s3.w += v7.w;
    }

    const float inv_t = 1.0f / T_DIM;
    float4 a;
    a.x = (s0.x + s1.x + s2.x + s3.x) * inv_t;
    a.y = (s0.y + s1.y + s2.y + s3.y) * inv_t;
    a.z = (s0.z + s1.z + s2.z + s3.z) * inv_t;
    a.w = (s0.w + s1.w + s2.w + s3.w) * inv_t;

    // Per-thread partials: ||a||^2 and 8 dots with c_l
    float asq = a.x * a.x + a.y * a.y + a.z * a.z + a.w * a.w;
    float dot[NUM_LABELS];
#pragma unroll
    for (int l = 0; l < NUM_LABELS; ++l) {
        float4 cv = reinterpret_cast<const float4*>(g_c + l * D_DIM)[tid];
        dot[l] = a.x * cv.x + a.y * cv.y + a.z * cv.z + a.w * cv.w;
    }

    // Warp-level reduce 9 values, then cross-warp via smem
    const unsigned FULL = 0xFFFFFFFFu;
#pragma unroll
    for (int off = 16; off > 0; off >>= 1) {
        asq += __shfl_xor_sync(FULL, asq, off);
#pragma unroll
        for (int l = 0; l < NUM_LABELS; ++l)
            dot[l] += __shfl_xor_sync(FULL, dot[l], off);
    }

    __shared__ float part[8][12];  // 8 warps x (8 dots + asq), padded
    const int wid = tid >> 5;
    if ((tid & 31) == 0) {
#pragma unroll
        for (int l = 0; l < NUM_LABELS; ++l) part[wid][l] = dot[l];
        part[wid][8] = asq;
    }
    __syncthreads();

    if (tid < NUM_LABELS) {
        const int l = tid;
        float dl = 0.0f, aq = 0.0f;
#pragma unroll
        for (int w = 0; w < 8; ++w) {
            dl += part[w][l];
            aq += part[w][8];
        }
        float sl = (g_sqpart[l * 4 + 0] + g_sqpart[l * 4 + 1] +
                    g_sqpart[l * 4 + 2] + g_sqpart[l * 4 + 3]) * (1.0f / NUM_PROTOS);
        out[(size_t)b * NUM_LABELS + l] = 2.0f * dl - aq - sl;
    }
}

extern "C" void kernel_launch(void* const* d_in, const int* in_sizes, int n_in,
                              void* d_out, int out_size) {
    const float* h = (const float*)d_in[0];   // hidden_states [B, T, D]
    const float* w = (const float*)d_in[1];   // prototype_weight [512, D]
    float* out = (float*)d_out;               // [B, 8]

    proto_fold_kernel<<<32, 256>>>(w);
    pool_proto_kernel<<<B_DIM, 256>>>(h, out);
}

// round 2
// speedup vs baseline: 1.0006x; 1.0006x over previous
#include <cuda_runtime.h>
#include <cstdint>

// Problem constants (fixed by the reference)
#define B_DIM 1024
#define T_DIM 256
#define D_DIM 1024
#define NUM_LABELS 8
#define NUM_PROTOS 64   // per label; M = 512 total

// Device scratch (no cudaMalloc allowed)
__device__ float g_c[NUM_LABELS * D_DIM];   // c_l[d] = mean_p w[8p+l][d]   (32 KB)
__device__ float g_sqpart[NUM_LABELS * 4];  // partial sums of w^2 per (l, d-chunk)

// ---------------------------------------------------------------------------
// Prep: fold prototype_weight [512, 1024] into c[8][1024] and sqpart[8][4].
// Grid: 32 blocks (l = blk>>2, chunk = blk&3), 256 threads (one d each).
// Runs CONCURRENTLY with the streaming phase of pool_proto_kernel via PDL.
// ---------------------------------------------------------------------------
__global__ void proto_fold_kernel(const float* __restrict__ w) {
    const int l     = blockIdx.x >> 2;
    const int chunk = blockIdx.x & 3;
    const int d     = chunk * 256 + threadIdx.x;

    float sum = 0.0f, sq = 0.0f;
#pragma unroll 8
    for (int p = 0; p < NUM_PROTOS; ++p) {
        float v = w[(size_t)((p << 3) + l) * D_DIM + d];
        sum += v;
        sq  += v * v;
    }
    g_c[l * D_DIM + d] = sum * (1.0f / NUM_PROTOS);

    // block-reduce sq
    __shared__ float red[256];
    red[threadIdx.x] = sq;
    __syncthreads();
    for (int s = 128; s > 0; s >>= 1) {
        if (threadIdx.x < s) red[threadIdx.x] += red[threadIdx.x + s];
        __syncthreads();
    }
    if (threadIdx.x == 0) g_sqpart[blockIdx.x] = red[0];
}

// ---------------------------------------------------------------------------
// Main: one block per batch row b.
//   a[b,:] = (1/T) sum_t h[b,t,:]        (streamed, 256 KB per block)
//   out[b,l] = 2 * a.c_l - ||a||^2 - s_l
// 256 threads; each thread owns 4 consecutive d's (float4).
// The streaming phase is independent of proto_fold_kernel; we only
// cudaGridDependencySynchronize() before the epilogue reads g_c/g_sqpart.
// ---------------------------------------------------------------------------
__global__ __launch_bounds__(256, 8)
void pool_proto_kernel(const float* __restrict__ h, float* __restrict__ out) {
    const int b   = blockIdx.x;
    const int tid = threadIdx.x;

    // Base: float4 view of h[b, 0, tid*4]
    const float4* hp = reinterpret_cast<const float4*>(h)
                       + (size_t)b * T_DIM * (D_DIM / 4) + tid;

    float4 s0 = {0,0,0,0}, s1 = {0,0,0,0}, s2 = {0,0,0,0}, s3 = {0,0,0,0};

    // Stream T=256 rows, unroll 8 -> high MLP per thread, __ldcs (no reuse)
#pragma unroll 4
    for (int t = 0; t < T_DIM; t += 8) {
        float4 v0 = __ldcs(hp + (size_t)(t + 0) * 256);
        float4 v1 = __ldcs(hp + (size_t)(t + 1) * 256);
        float4 v2 = __ldcs(hp + (size_t)(t + 2) * 256);
        float4 v3 = __ldcs(hp + (size_t)(t + 3) * 256);
        float4 v4 = __ldcs(hp + (size_t)(t + 4) * 256);
        float4 v5 = __ldcs(hp + (size_t)(t + 5) * 256);
        float4 v6 = __ldcs(hp + (size_t)(t + 6) * 256);
        float4 v7 = __ldcs(hp + (size_t)(t + 7) * 256);
        s0.x += v0.x; s0.y += v0.y; s0.z += v0.z; s0.w += v0.w;
        s1.x += v1.x; s1.y += v1.y; s1.z += v1.z; s1.w += v1.w;
        s2.x += v2.x; s2.y += v2.y; s2.z += v2.z; s2.w += v2.w;
        s3.x += v3.x; s3.y += v3.y; s3.z += v3.z; s3.w += v3.w;
        s0.x += v4.x; s0.y += v4.y; s0.z += v4.z; s0.w += v4.w;
        s1.x += v5.x; s1.y += v5.y; s1.z += v5.z; s1.w += v5.w;
        s2.x += v6.x; s2.y += v6.y; s2.z += v6.z; s2.w += v6.w;
        s3.x += v7.x; s3.y += v7.y; s3.z += v7.z; s3.w += v7.w;
    }

    const float inv_t = 1.0f / T_DIM;
    float4 a;
    a.x = (s0.x + s1.x + s2.x + s3.x) * inv_t;
    a.y = (s0.y + s1.y + s2.y + s3.y) * inv_t;
    a.z = (s0.z + s1.z + s2.z + s3.z) * inv_t;
    a.w = (s0.w + s1.w + s2.w + s3.w) * inv_t;

    float asq = a.x * a.x + a.y * a.y + a.z * a.z + a.w * a.w;

    // Wait for proto_fold_kernel's results (PDL edge); by now it finished
    // ~148us ago, so this never actually stalls.
    cudaGridDependencySynchronize();

    // Per-thread partials: 8 dots with c_l (L2-resident, 32 KB shared by all blocks)
    float dot[NUM_LABELS];
#pragma unroll
    for (int l = 0; l < NUM_LABELS; ++l) {
        float4 cv = reinterpret_cast<const float4*>(g_c + l * D_DIM)[tid];
        dot[l] = a.x * cv.x + a.y * cv.y + a.z * cv.z + a.w * cv.w;
    }

    // Warp-level reduce 9 values, then cross-warp via smem
    const unsigned FULL = 0xFFFFFFFFu;
#pragma unroll
    for (int off = 16; off > 0; off >>= 1) {
        asq += __shfl_xor_sync(FULL, asq, off);
#pragma unroll
        for (int l = 0; l < NUM_LABELS; ++l)
            dot[l] += __shfl_xor_sync(FULL, dot[l], off);
    }

    __shared__ float part[8][12];  // 8 warps x (8 dots + asq), padded
    const int wid = tid >> 5;
    if ((tid & 31) == 0) {
#pragma unroll
        for (int l = 0; l < NUM_LABELS; ++l) part[wid][l] = dot[l];
        part[wid][8] = asq;
    }
    __syncthreads();

    if (tid < NUM_LABELS) {
        const int l = tid;
        float dl = 0.0f, aq = 0.0f;
#pragma unroll
        for (int w = 0; w < 8; ++w) {
            dl += part[w][l];
            aq += part[w][8];
        }
        float sl = (g_sqpart[l * 4 + 0] + g_sqpart[l * 4 + 1] +
                    g_sqpart[l * 4 + 2] + g_sqpart[l * 4 + 3]) * (1.0f / NUM_PROTOS);
        out[(size_t)b * NUM_LABELS + l] = 2.0f * dl - aq - sl;
    }
}

extern "C" void kernel_launch(void* const* d_in, const int* in_sizes, int n_in,
                              void* d_out, int out_size) {
    const float* h = (const float*)d_in[0];   // hidden_states [B, T, D]
    const float* w = (const float*)d_in[1];   // prototype_weight [512, D]
    float* out = (float*)d_out;               // [B, 8]

    // 1) Fold kernel: small, launched first so its 32 blocks get resident
    //    before the pool grid fills the machine.
    proto_fold_kernel<<<32, 256>>>(w);

    // 2) Pool kernel with Programmatic Dependent Launch: starts streaming
    //    immediately (overlapping the fold), syncs on the fold only at the
    //    epilogue via cudaGridDependencySynchronize().
    cudaLaunchConfig_t cfg = {};
    cfg.gridDim  = dim3(B_DIM);
    cfg.blockDim = dim3(256);
    cfg.dynamicSmemBytes = 0;
    cfg.stream = 0;

    cudaLaunchAttribute attrs[1];
    attrs[0].id = cudaLaunchAttributeProgrammaticStreamSerialization;
    attrs[0].val.programmaticStreamSerializationAllowed = 1;
    cfg.attrs = attrs;
    cfg.numAttrs = 1;

    cudaLaunchKernelEx(&cfg, pool_proto_kernel, h, out);
}